// round 2
// baseline (speedup 1.0000x reference)
#include <cuda_runtime.h>
#include <cstdint>

#define SAMPLE 8192
#define KNN 8
#define EPSV 1e-12f
// Sentinel for empty top-9 slots: d2 field = +inf (valid float!), idx = ~0.
// Using all-ones here was the R1 bug: its d2 field decodes to NaN and the
// `d2 <= w8` prefilter rejects everything after the first insert.
#define SENT 0x7F800000FFFFFFFFull

// Packed gathered points: (x, y, z, |p|^2) and sh0 (x, y, z, 0)
__device__ float4 g_P[SAMPLE];
__device__ float4 g_S[SAMPLE];

__global__ void gather_kernel(const float* __restrict__ means,
                              const float* __restrict__ sh0,
                              const int* __restrict__ idx_raw) {
    int i = blockIdx.x * blockDim.x + threadIdx.x;
    if (i >= SAMPLE) return;
    // Detect int64 vs int32 index layout: little-endian int64 with values
    // < 2^31 has all odd int32 words zero.
    bool is64 = ((idx_raw[1] | idx_raw[3] | idx_raw[5] | idx_raw[7] |
                  idx_raw[9] | idx_raw[11] | idx_raw[13] | idx_raw[15]) == 0);
    long long j = is64 ? ((const long long*)idx_raw)[i] : (long long)idx_raw[i];
    float x = means[3 * j + 0];
    float y = means[3 * j + 1];
    float z = means[3 * j + 2];
    float sq = fmaf(z, z, fmaf(y, y, x * x));
    g_P[i] = make_float4(x, y, z, sq);
    g_S[i] = make_float4(sh0[3 * j + 0], sh0[3 * j + 1], sh0[3 * j + 2], 0.f);
}

// One warp per query point. 8 warps (8 queries) per block share smem tiles.
__global__ void __launch_bounds__(256) knn_loss_kernel(float* __restrict__ out) {
    __shared__ float4 sP[256];
    const int lane = threadIdx.x & 31;
    const int warp = threadIdx.x >> 5;
    const int i = blockIdx.x * 8 + warp;
    const float4 pi = g_P[i];

    // Per-lane sorted ascending top-9 of u64 keys: (d2_bits << 32) | j
    unsigned long long heap[9];
#pragma unroll
    for (int k = 0; k < 9; k++) heap[k] = SENT;
    float w8 = __int_as_float(0x7f800000);  // d2 of current 9th-best (+inf)

    for (int t = 0; t < SAMPLE; t += 256) {
        __syncthreads();
        sP[threadIdx.x] = g_P[t + threadIdx.x];
        __syncthreads();
#pragma unroll
        for (int u = 0; u < 8; u++) {
            int jj = u * 32 + lane;
            float4 pj = sP[jj];
            float dot = fmaf(pi.z, pj.z, fmaf(pi.y, pj.y, pi.x * pj.x));
            float d2 = fmaf(-2.f, dot, pi.w + pj.w);
            d2 = fmaxf(d2, EPSV);
            if (d2 <= w8) {  // cheap prefilter; <= keeps index tie-break correct
                unsigned long long key =
                    ((unsigned long long)__float_as_uint(d2) << 32) |
                    (unsigned)(t + jj);
                if (key < heap[8]) {
                    unsigned long long cur = key;
#pragma unroll
                    for (int k = 0; k < 9; k++) {
                        unsigned long long h = heap[k];
                        bool lt = cur < h;
                        heap[k] = lt ? cur : h;
                        cur = lt ? h : cur;
                    }
                    w8 = __uint_as_float((unsigned)(heap[8] >> 32));
                }
            }
        }
    }

    // Warp merge: 9 rounds of butterfly min over each lane's list head.
    // Real keys are unique across lanes (distinct j per lane), so exactly one
    // lane pops per round; each lane holds 9 real keys so sentinels never win.
    unsigned long long mykey = SENT;
#pragma unroll
    for (int r = 0; r < 9; r++) {
        unsigned long long cand = heap[0];
        unsigned long long m = cand;
#pragma unroll
        for (int o = 16; o > 0; o >>= 1) {
            unsigned long long other = __shfl_xor_sync(0xFFFFFFFFu, m, o);
            m = (other < m) ? other : m;
        }
        if (cand == m) {
            // pop head: static-index shift (keeps heap in registers)
#pragma unroll
            for (int k = 0; k < 8; k++) heap[k] = heap[k + 1];
            heap[8] = SENT;
        }
        if (lane == r) mykey = m;  // r is compile-time constant (unrolled)
    }

    // Ranks 1..8 (rank 0 = self / tied duplicate, excluded like knn_idx[:,1:])
    float contrib = 0.f;
    if (lane >= 1 && lane <= KNN) {
        int j = (int)(mykey & 0xFFFFFFFFu);
        float d2 = __uint_as_float((unsigned)(mykey >> 32));  // already clamped
        float dist = sqrtf(d2);
        float w = __expf(-dist);
        float4 si = g_S[i];
        float4 sj = g_S[j];
        float dx = si.x - sj.x, dy = si.y - sj.y, dz = si.z - sj.z;
        contrib = w * (dx * dx + dy * dy + dz * dz);
    }
#pragma unroll
    for (int o = 16; o > 0; o >>= 1)
        contrib += __shfl_xor_sync(0xFFFFFFFFu, contrib, o);
    if (lane == 0)
        atomicAdd(out, contrib * (1.f / (float)(SAMPLE * KNN * 3)));
}

extern "C" void kernel_launch(void* const* d_in, const int* in_sizes, int n_in,
                              void* d_out, int out_size) {
    const float* means = (const float*)d_in[0];
    const float* sh0 = (const float*)d_in[1];
    const int* idx = (const int*)d_in[2];
    float* out = (float*)d_out;

    gather_kernel<<<SAMPLE / 256, 256>>>(means, sh0, idx);
    cudaMemsetAsync(out, 0, sizeof(float), 0);
    knn_loss_kernel<<<SAMPLE / 8, 256>>>(out);
}

// round 3
// speedup vs baseline: 1.1943x; 1.1943x over previous
#include <cuda_runtime.h>
#include <cstdint>

#define SAMPLE 8192
#define KNN 8
#define EPSV 1e-12f
// Sentinel for empty top-9 slots: d2 field = +inf (valid float), idx = ~0.
#define SENT 0x7F800000FFFFFFFFull

// g_P: (x, y, z, |p|^2) for the query side.
// g_Q: (-2x, -2y, -2z, |p|^2) for the tile side, so
//   d2 = (wi + wj) + qx*xi + qy*yi + qz*zi   (1 FADD + 3 FFMA)
__device__ float4 g_P[SAMPLE];
__device__ float4 g_Q[SAMPLE];
__device__ float4 g_S[SAMPLE];

__global__ void gather_kernel(const float* __restrict__ means,
                              const float* __restrict__ sh0,
                              const int* __restrict__ idx_raw) {
    int i = blockIdx.x * blockDim.x + threadIdx.x;
    if (i >= SAMPLE) return;
    // Detect int64 vs int32 index layout: little-endian int64 values < 2^31
    // have all odd int32 words zero.
    bool is64 = ((idx_raw[1] | idx_raw[3] | idx_raw[5] | idx_raw[7] |
                  idx_raw[9] | idx_raw[11] | idx_raw[13] | idx_raw[15]) == 0);
    long long j = is64 ? ((const long long*)idx_raw)[i] : (long long)idx_raw[i];
    float x = means[3 * j + 0];
    float y = means[3 * j + 1];
    float z = means[3 * j + 2];
    float sq = fmaf(z, z, fmaf(y, y, x * x));
    g_P[i] = make_float4(x, y, z, sq);
    g_Q[i] = make_float4(-2.f * x, -2.f * y, -2.f * z, sq);
    g_S[i] = make_float4(sh0[3 * j + 0], sh0[3 * j + 1], sh0[3 * j + 2], 0.f);
}

// One warp per query point. 8 warps (8 queries) per block share smem tiles.
__global__ void __launch_bounds__(256) knn_loss_kernel(float* __restrict__ out) {
    __shared__ float4 sQ[256];
    const int lane = threadIdx.x & 31;
    const int warp = threadIdx.x >> 5;
    const int i = blockIdx.x * 8 + warp;
    const float4 pi = g_P[i];

    // Per-lane sorted ascending top-9 of u64 keys: (d2_bits << 32) | j
    unsigned long long heap[9];
#pragma unroll
    for (int k = 0; k < 9; k++) heap[k] = SENT;
    // Warp-uniform accept threshold: upper bound on the warp-global 9th-best
    // d2 (refreshed once per tile as min over lanes of each lane's 9th-best).
    float w8 = __int_as_float(0x7f800000);

    for (int t = 0; t < SAMPLE; t += 256) {
        __syncthreads();
        sQ[threadIdx.x] = g_Q[t + threadIdx.x];
        __syncthreads();
#pragma unroll
        for (int u = 0; u < 8; u++) {
            int jj = u * 32 + lane;
            float4 qj = sQ[jj];
            float d2 = qj.w + pi.w;
            d2 = fmaf(qj.x, pi.x, d2);
            d2 = fmaf(qj.y, pi.y, d2);
            d2 = fmaf(qj.z, pi.z, d2);
            // Raw d2 may be slightly negative (self/dups); raw <= clamped, so
            // comparing raw against the clamped-based threshold is safe.
            if (d2 <= w8) {
                float d2c = fmaxf(d2, EPSV);
                unsigned long long key =
                    ((unsigned long long)__float_as_uint(d2c) << 32) |
                    (unsigned)(t + jj);
                if (key < heap[8]) {
                    unsigned long long cur = key;
#pragma unroll
                    for (int k = 0; k < 9; k++) {
                        unsigned long long h = heap[k];
                        bool lt = cur < h;
                        heap[k] = lt ? cur : h;
                        cur = lt ? h : cur;
                    }
                }
            }
        }
        // Refresh warp-uniform threshold (butterfly min -> uniform result).
        float l8 = __uint_as_float((unsigned)(heap[8] >> 32));
#pragma unroll
        for (int o = 16; o > 0; o >>= 1)
            l8 = fminf(l8, __shfl_xor_sync(0xFFFFFFFFu, l8, o));
        w8 = l8;
    }

    // Warp merge: 9 rounds of butterfly min over each lane's list head.
    // >=9 real keys exist warp-wide (the global top-9 all pass the filter and
    // are retained); real keys are unique (distinct j), lists are sorted, so
    // the warp-min head is a real key and exactly one lane pops per round.
    unsigned long long mykey = SENT;
#pragma unroll
    for (int r = 0; r < 9; r++) {
        unsigned long long cand = heap[0];
        unsigned long long m = cand;
#pragma unroll
        for (int o = 16; o > 0; o >>= 1) {
            unsigned long long other = __shfl_xor_sync(0xFFFFFFFFu, m, o);
            m = (other < m) ? other : m;
        }
        if (cand == m) {
#pragma unroll
            for (int k = 0; k < 8; k++) heap[k] = heap[k + 1];
            heap[8] = SENT;
        }
        if (lane == r) mykey = m;
    }

    // Ranks 1..8 (rank 0 = self / tied duplicate, excluded like knn_idx[:,1:])
    float contrib = 0.f;
    if (lane >= 1 && lane <= KNN) {
        int j = (int)(mykey & 0xFFFFFFFFu);
        float d2 = __uint_as_float((unsigned)(mykey >> 32));
        float dist = sqrtf(d2);
        float w = __expf(-dist);
        float4 si = g_S[i];
        float4 sj = g_S[j];
        float dx = si.x - sj.x, dy = si.y - sj.y, dz = si.z - sj.z;
        contrib = w * (dx * dx + dy * dy + dz * dz);
    }
#pragma unroll
    for (int o = 16; o > 0; o >>= 1)
        contrib += __shfl_xor_sync(0xFFFFFFFFu, contrib, o);
    if (lane == 0)
        atomicAdd(out, contrib * (1.f / (float)(SAMPLE * KNN * 3)));
}

extern "C" void kernel_launch(void* const* d_in, const int* in_sizes, int n_in,
                              void* d_out, int out_size) {
    const float* means = (const float*)d_in[0];
    const float* sh0 = (const float*)d_in[1];
    const int* idx = (const int*)d_in[2];
    float* out = (float*)d_out;

    gather_kernel<<<SAMPLE / 256, 256>>>(means, sh0, idx);
    cudaMemsetAsync(out, 0, sizeof(float), 0);
    knn_loss_kernel<<<SAMPLE / 8, 256>>>(out);
}